// round 15
// baseline (speedup 1.0000x reference)
#include <cuda_runtime.h>
#include <cuda_fp16.h>
#include <cstdint>
#include <cstddef>

// Problem dims (fixed)
#define M1 16384      // b*t*s = 16*4*256
#define K1 512        // d
#define N1 2048       // hidden
#define N2 512
#define HID 2048
#define N_SPIKES 33554432.0f  // 2^25

#define TAU 4e-3f
#define NGQ 4096      // distinct (b*256+s) groups

// ---------------------------------------------------------------------------
// Device scratch. No x16 tensor — fc1's loader converts fp32 x on the fly.
// Row order for spk is PERMUTED: row' = (b*256 + s)*4 + t.
// ---------------------------------------------------------------------------
__device__ __half    g_w1h[(size_t)N1 * K1];     // fp16(w1)
__device__ __half    g_spk[(size_t)M1 * HID];    // spikes (fp16), (b,s,t) rows
__device__ __half    g_w2h[(size_t)N2 * HID];    // fp16(w2)
__device__ int       g_count;
__device__ uint32_t  g_flagbits[NGQ * 64];       // per-(gq, j-block) borderline mask

// ---------------------------------------------------------------------------
// PTX helpers
// ---------------------------------------------------------------------------
__device__ __forceinline__ uint32_t smem_u32(const void* p) {
    uint32_t a;
    asm("{ .reg .u64 t; cvta.to.shared.u64 t, %1; cvt.u32.u64 %0, t; }" : "=r"(a) : "l"(p));
    return a;
}
__device__ __forceinline__ void cp16(uint32_t saddr, const void* g) {
    asm volatile("cp.async.cg.shared.global [%0], [%1], 16;" :: "r"(saddr), "l"(g));
}
__device__ __forceinline__ void ldm_x4(uint32_t* r, uint32_t addr) {
    asm volatile("ldmatrix.sync.aligned.m8n8.x4.shared.b16 {%0,%1,%2,%3}, [%4];"
        : "=r"(r[0]), "=r"(r[1]), "=r"(r[2]), "=r"(r[3]) : "r"(addr));
}
__device__ __forceinline__ void mma16816(float* c, const uint32_t* a, uint32_t b0, uint32_t b1) {
    asm volatile("mma.sync.aligned.m16n8k16.row.col.f32.f16.f16.f32 "
        "{%0,%1,%2,%3}, {%4,%5,%6,%7}, {%8,%9}, {%0,%1,%2,%3};"
        : "+f"(c[0]), "+f"(c[1]), "+f"(c[2]), "+f"(c[3])
        : "r"(a[0]), "r"(a[1]), "r"(a[2]), "r"(a[3]), "r"(b0), "r"(b1));
}
__device__ __forceinline__ uint32_t f2h2(float a, float b) {
    __half2 h = __floats2half2_rn(a, b);
    return *(uint32_t*)&h;
}

// ---------------------------------------------------------------------------
// GEMM config: 128x128x64 tiles, 3-stage pipeline, 8 warps (32x64 per warp).
// Both GEMMs use the identical fp16 swizzled smem layout (LDSM path = R13).
// ---------------------------------------------------------------------------
#define BM 128
#define BN 128
#define BK 64
#define STAGES 3
#define A_STAGE_BYTES (BM * BK * 2)                 // 16384
#define STAGE_BYTES   (A_STAGE_BYTES + BN * BK * 2) // 32768
#define SMEM_TOTAL    (STAGES * STAGE_BYTES)        // 98304 (>= 128*132*4 epi)

// fc2 loader: both operands fp16 via cp.async
__device__ __forceinline__ void load_stage_f16(uint32_t s_stage, const __half* Ag,
                                               const __half* Bg, int K, int k0, int tid) {
#pragma unroll
    for (int i = 0; i < 4; i++) {
        int c = tid + i * 256;
        int row = c >> 3, kc = c & 7;
        cp16(s_stage + row * 128 + ((kc ^ (row & 7)) << 4), Ag + (long)row * K + k0 + kc * 8);
    }
#pragma unroll
    for (int i = 0; i < 4; i++) {
        int c = tid + i * 256;
        int row = c >> 3, kc = c & 7;
        cp16(s_stage + A_STAGE_BYTES + row * 128 + ((kc ^ (row & 7)) << 4),
             Bg + (long)row * K + k0 + kc * 8);
    }
}

// fc1 loader: A = fp32 x, converted in the loader (LDG.128 x2 -> cvt -> STS.128)
// into the SAME swizzled fp16 layout; (b,t,s)->(b,s,t) permutation folded into
// the global address. B = fp16 w1h via cp.async. Rounding = __floats2half2_rn,
// bit-identical to the old prep path.
__device__ __forceinline__ void load_stage_fc1(char* sm_stage, uint32_t s_stage_u32,
                                               const float* xg, const __half* Bg,
                                               long bm, int k0, int tid) {
#pragma unroll
    for (int i = 0; i < 4; i++) {
        int c = tid + i * 256;
        int row = c >> 3, kc = c & 7;      // 8 halfs per chunk
        long rp = bm + row;
        long b = rp >> 10, s = (rp >> 2) & 255, t = rp & 3;
        const float4* g = (const float4*)(xg + (((b * 4 + t) * 256 + s) << 9) + k0 + kc * 8);
        float4 v0 = __ldg(g);
        float4 v1 = __ldg(g + 1);
        uint4 u;
        u.x = f2h2(v0.x, v0.y);
        u.y = f2h2(v0.z, v0.w);
        u.z = f2h2(v1.x, v1.y);
        u.w = f2h2(v1.z, v1.w);
        *(uint4*)(sm_stage + row * 128 + ((kc ^ (row & 7)) << 4)) = u;
    }
#pragma unroll
    for (int i = 0; i < 4; i++) {
        int c = tid + i * 256;
        int row = c >> 3, kc = c & 7;
        cp16(s_stage_u32 + A_STAGE_BYTES + row * 128 + ((kc ^ (row & 7)) << 4),
             Bg + (long)row * K1 + k0 + kc * 8);
    }
}

// Fragment load for one k16 step into register buffer `buf` (fp16 LDSM path)
#define LOAD_FRAG(buf, sa_, sb_, ks_) do {                                         \
    const int kch_ = ((ks_) << 1) + (lane >> 4);                                   \
    _Pragma("unroll")                                                              \
    for (int mt = 0; mt < 2; mt++) {                                               \
        int row = wm * 32 + mt * 16 + (lane & 15);                                 \
        ldm_x4(arf[buf][mt], (sa_) + row * 128 + ((kch_ ^ (row & 7)) << 4));       \
    }                                                                              \
    _Pragma("unroll")                                                              \
    for (int np = 0; np < 4; np++) {                                               \
        int row = wn * 64 + np * 16 + (lane & 15);                                 \
        ldm_x4(brf[buf][np], (sb_) + row * 128 + ((kch_ ^ (row & 7)) << 4));       \
    }                                                                              \
} while (0)

#define MMA_BLOCK(cur)                                                             \
    _Pragma("unroll")                                                              \
    for (int mt = 0; mt < 2; mt++)                                                 \
        _Pragma("unroll")                                                          \
        for (int nt = 0; nt < 8; nt++)                                             \
            mma16816(acc[mt][nt], arf[cur][mt], brf[cur][nt >> 1][nt & 1],         \
                     brf[cur][nt >> 1][(nt & 1) + 2]);

// ---------------------------------------------------------------------------
// fc1 + fused LIF: A converted from fp32 x in the loader; epilogue scans t,
// writes fp16 spikes, emits flag bitmask, counts unflagged spikes.
// ---------------------------------------------------------------------------
__global__ __launch_bounds__(256, 2) void hgemm_fc1_lif(const float* __restrict__ x,
                                                        const __half* __restrict__ B) {
    extern __shared__ char sm[];
    const uint32_t s_base = smem_u32(sm);
    const int tid = threadIdx.x;
    const int wid = tid >> 5, lane = tid & 31;
    const int wm = wid & 3;
    const int wn = wid >> 2;
    const long bm = (long)blockIdx.y * BM;
    const long bn = (long)blockIdx.x * BN;

    const __half* Bg = B + bn * K1;

    float acc[2][8][4];
    uint32_t arf[2][2][4];
    uint32_t brf[2][4][4];
#pragma unroll
    for (int mt = 0; mt < 2; mt++)
#pragma unroll
        for (int nt = 0; nt < 8; nt++)
#pragma unroll
            for (int i = 0; i < 4; i++) acc[mt][nt][i] = 0.0f;

    const int iters = K1 / BK;   // 8
    load_stage_fc1(sm, s_base, x, Bg, bm, 0, tid);
    asm volatile("cp.async.commit_group;" ::: "memory");
    load_stage_fc1(sm + STAGE_BYTES, s_base + STAGE_BYTES, x, Bg, bm, BK, tid);
    asm volatile("cp.async.commit_group;" ::: "memory");

    for (int it = 0; it < iters; it++) {
        asm volatile("cp.async.wait_group 1;" ::: "memory");
        __syncthreads();
        const uint32_t sa = s_base + (it % STAGES) * STAGE_BYTES;
        const uint32_t sb = sa + A_STAGE_BYTES;
        LOAD_FRAG(0, sa, sb, 0);
        const int nst = it + 2;
        if (nst < iters) {
            int so = (nst % STAGES) * STAGE_BYTES;
            load_stage_fc1(sm + so, s_base + so, x, Bg, bm, nst * BK, tid);
        }
        asm volatile("cp.async.commit_group;" ::: "memory");
#pragma unroll
        for (int ks = 0; ks < 4; ks++) {
            const int cur = ks & 1;
            if (ks < 3) LOAD_FRAG(cur ^ 1, sa, sb, ks + 1);
            MMA_BLOCK(cur)
        }
    }

    asm volatile("cp.async.wait_group 0;" ::: "memory");
    __syncthreads();

    // spill accumulators to smem: h[row within tile][col within tile]
    float* smf = (float*)sm;                 // [128][132]
#pragma unroll
    for (int mt = 0; mt < 2; mt++)
#pragma unroll
        for (int nt = 0; nt < 8; nt++) {
            int r0 = wm * 32 + mt * 16 + (lane >> 2);
            int c  = wn * 64 + nt * 8 + (lane & 3) * 2;
            smf[r0 * 132 + c]       = acc[mt][nt][0];
            smf[r0 * 132 + c + 1]   = acc[mt][nt][1];
            smf[(r0 + 8) * 132 + c]     = acc[mt][nt][2];
            smf[(r0 + 8) * 132 + c + 1] = acc[mt][nt][3];
        }
    __syncthreads();

    // LIF scan: 32 groups x 128 cols; ballot -> flag word per 32 cols.
    const __half one  = __float2half_rn(1.0f);
    const __half zero = __float2half_rn(0.0f);
    int total = 0;
#pragma unroll
    for (int k16 = 0; k16 < 16; k16++) {
        int id = tid + k16 * 256;
        int q  = id >> 7;
        int c  = id & 127;
        long gq = blockIdx.y * 32 + q;
        long j  = bn + c;

        float v = 0.0f;
        int cnt = 0;
        bool flagged = false;
#pragma unroll
        for (int t = 0; t < 4; t++) {
            float h = smf[(4 * q + t) * 132 + c];
            v = fmaf(0.95f, v, h);
            flagged |= fabsf(v - 1.0f) < TAU;
            bool fire = (v - 1.0f) > 0.0f;
            g_spk[(gq * 4 + t) * HID + j] = fire ? one : zero;
            cnt += fire ? 1 : 0;
            v = fire ? 0.0f : v;
        }
        uint32_t fmask = __ballot_sync(0xffffffffu, flagged);
        if (lane == 0)
            g_flagbits[gq * 64 + (j >> 5)] = fmask;
        if (!flagged) total += cnt;
    }
#pragma unroll
    for (int o = 16; o > 0; o >>= 1) total += __shfl_down_sync(0xffffffffu, total, o);
    if (lane == 0 && total) atomicAdd(&g_count, total);
}

// ---------------------------------------------------------------------------
// fc2: spikes (fp16) x w2h; epilogue un-permutes rows (b,s,t)->(b,t,s).
// ---------------------------------------------------------------------------
__global__ __launch_bounds__(256, 2) void hgemm_fc2(const __half* __restrict__ A,
                                                    const __half* __restrict__ B,
                                                    float* __restrict__ C) {
    extern __shared__ char sm[];
    const uint32_t s_base = smem_u32(sm);
    const int tid = threadIdx.x;
    const int wid = tid >> 5, lane = tid & 31;
    const int wm = wid & 3;
    const int wn = wid >> 2;
    const long bm = (long)blockIdx.y * BM;
    const long bn = (long)blockIdx.x * BN;

    const __half* Ag = A + bm * HID;
    const __half* Bg = B + bn * HID;

    float acc[2][8][4];
    uint32_t arf[2][2][4];
    uint32_t brf[2][4][4];
#pragma unroll
    for (int mt = 0; mt < 2; mt++)
#pragma unroll
        for (int nt = 0; nt < 8; nt++)
#pragma unroll
            for (int i = 0; i < 4; i++) acc[mt][nt][i] = 0.0f;

    const int iters = HID / BK;
    load_stage_f16(s_base, Ag, Bg, HID, 0, tid);
    asm volatile("cp.async.commit_group;" ::: "memory");
    load_stage_f16(s_base + STAGE_BYTES, Ag, Bg, HID, BK, tid);
    asm volatile("cp.async.commit_group;" ::: "memory");
    for (int it = 0; it < iters; it++) {
        asm volatile("cp.async.wait_group 1;" ::: "memory");
        __syncthreads();
        const uint32_t sa = s_base + (it % STAGES) * STAGE_BYTES;
        const uint32_t sb = sa + A_STAGE_BYTES;
        LOAD_FRAG(0, sa, sb, 0);
        const int nst = it + 2;
        if (nst < iters)
            load_stage_f16(s_base + (nst % STAGES) * STAGE_BYTES, Ag, Bg, HID, nst * BK, tid);
        asm volatile("cp.async.commit_group;" ::: "memory");
#pragma unroll
        for (int ks = 0; ks < 4; ks++) {
            const int cur = ks & 1;
            if (ks < 3) LOAD_FRAG(cur ^ 1, sa, sb, ks + 1);
            MMA_BLOCK(cur)
        }
    }

    // epilogue: map row' (b,s,t) -> out row (b,t,s)
#pragma unroll
    for (int mt = 0; mt < 2; mt++)
#pragma unroll
        for (int nt = 0; nt < 8; nt++) {
            long rp0 = bm + wm * 32 + mt * 16 + (lane >> 2);
            long rp1 = rp0 + 8;
            long c = bn + wn * 64 + nt * 8 + (lane & 3) * 2;
            long b0 = rp0 >> 10, s0 = (rp0 >> 2) & 255, t0 = rp0 & 3;
            long b1 = rp1 >> 10, s1 = (rp1 >> 2) & 255, t1 = rp1 & 3;
            long r0 = b0 * 1024 + t0 * 256 + s0;
            long r1 = b1 * 1024 + t1 * 256 + s1;
            *(float2*)(C + r0 * N2 + c) = make_float2(acc[mt][nt][0], acc[mt][nt][1]);
            *(float2*)(C + r1 * N2 + c) = make_float2(acc[mt][nt][2], acc[mt][nt][3]);
        }
}

// ---------------------------------------------------------------------------
// prep: weight casts only (x handled by fc1's loader / fixup directly)
// ---------------------------------------------------------------------------
#define W14  (N1 * K1 / 4)      // 262144
#define W24  (N2 * HID / 4)     // 262144

__global__ __launch_bounds__(256) void prep_kernel(const float* __restrict__ w1,
                                                   const float* __restrict__ w2) {
    int i = blockIdx.x * blockDim.x + threadIdx.x;
    if (i == 0) g_count = 0;
    if (i < W14) {
        float4 v = ((const float4*)w1)[i];
        ((__half2*)g_w1h)[2 * i]     = __floats2half2_rn(v.x, v.y);
        ((__half2*)g_w1h)[2 * i + 1] = __floats2half2_rn(v.z, v.w);
    } else if (i < W14 + W24) {
        int k = i - W14;
        float4 v = ((const float4*)w2)[k];
        ((__half2*)g_w2h)[2 * k]     = __floats2half2_rn(v.x, v.y);
        ((__half2*)g_w2h)[2 * k + 1] = __floats2half2_rn(v.z, v.w);
    }
}

// ---------------------------------------------------------------------------
// Parallel fixup v3 (proven bit-exact): one CTA per gq; thread = (neuron,
// timestep) quad; each h-chain is the serial ascending-k fp32 fmaf order.
// ---------------------------------------------------------------------------
__global__ __launch_bounds__(128) void fixup_kernel(const float* __restrict__ x,
                                                    const float* __restrict__ w1) {
    __shared__ float4 xs[4][128];
    __shared__ int    list[2048];
    __shared__ int    nlist;
    __shared__ int    blk_count;

    const int tid = threadIdx.x;
    const int lane = tid & 31;
    const int gq = blockIdx.x;
    const int b  = gq >> 8;
    const int s  = gq & 255;

    if (tid == 0) { nlist = 0; blk_count = 0; }
    __syncthreads();

    if (tid < 64) {
        uint32_t m = g_flagbits[(size_t)gq * 64 + tid];
        if (m) {
            int base = atomicAdd(&nlist, __popc(m));
            while (m) {
                int bit = __ffs(m) - 1;
                m &= m - 1;
                list[base++] = tid * 32 + bit;
            }
        }
    }
#pragma unroll
    for (int i = 0; i < 4; i++) {
        int idx = tid + i * 128;
        int row = idx >> 7, c4 = idx & 127;
        xs[row][c4] = __ldg((const float4*)(x + (((size_t)b * 4 + row) * 256 + s) * K1) + c4);
    }
    __syncthreads();

    const __half one  = __float2half_rn(1.0f);
    const __half zero = __float2half_rn(0.0f);

    const int n = nlist;
    const int tt = tid & 3;
    const int passes = (n + 31) >> 5;
    for (int p = 0; p < passes; p++) {
        int li = p * 32 + (tid >> 2);
        bool active = li < n;
        int j = active ? list[li] : 0;
        const float4* wrow = (const float4*)(w1 + (size_t)j * K1);
        float h = 0.0f;
#pragma unroll 8
        for (int k4 = 0; k4 < 128; k4++) {
            float4 wv = __ldg(wrow + k4);
            float4 xv = xs[tt][k4];
            h = fmaf(xv.x, wv.x, h);
            h = fmaf(xv.y, wv.y, h);
            h = fmaf(xv.z, wv.z, h);
            h = fmaf(xv.w, wv.w, h);
        }
        float hs[4];
#pragma unroll
        for (int k = 0; k < 4; k++)
            hs[k] = __shfl_sync(0xffffffffu, h, (lane & ~3) | k);
        if (active && tt == 0) {
            float v = 0.0f;
            int c = 0;
#pragma unroll
            for (int t2 = 0; t2 < 4; t2++) {
                v = fmaf(0.95f, v, hs[t2]);
                bool fire = (v - 1.0f) > 0.0f;
                g_spk[((size_t)gq * 4 + t2) * HID + j] = fire ? one : zero;
                c += fire ? 1 : 0;
                v = fire ? 0.0f : v;
            }
            if (c) atomicAdd(&blk_count, c);
        }
    }
    __syncthreads();
    if (tid == 0 && blk_count) atomicAdd(&g_count, blk_count);
}

__global__ void write_rate_kernel(float* __restrict__ out, int pos) {
    out[pos] = (float)g_count * (1.0f / N_SPIKES);  // exact: count / 2^25
}

// ---------------------------------------------------------------------------
extern "C" void kernel_launch(void* const* d_in, const int* in_sizes, int n_in,
                              void* d_out, int out_size) {
    const float* x  = (const float*)d_in[0];  // (16,4,256,512)
    const float* w1 = (const float*)d_in[1];  // (2048,512)
    const float* w2 = (const float*)d_in[2];  // (512,2048)
    float* out = (float*)d_out;

    __half *w1h, *spk, *w2h;
    cudaGetSymbolAddress((void**)&w1h, g_w1h);
    cudaGetSymbolAddress((void**)&spk, g_spk);
    cudaGetSymbolAddress((void**)&w2h, g_w2h);

    cudaFuncSetAttribute(hgemm_fc1_lif, cudaFuncAttributeMaxDynamicSharedMemorySize, SMEM_TOTAL);
    cudaFuncSetAttribute(hgemm_fc2, cudaFuncAttributeMaxDynamicSharedMemorySize, SMEM_TOTAL);

    dim3 blk(256);

    // weight casts only (also zeroes the spike counter)
    prep_kernel<<<(W14 + W24 + 255) / 256, blk>>>(w1, w2);

    // fc1 (loader-converted fp32 A) + fused LIF scan
    hgemm_fc1_lif<<<dim3(N1 / BN, M1 / BM), blk, SMEM_TOTAL>>>(x, w1h);

    // parallel exact fixup (quad tt-parallel serial-order chains)
    fixup_kernel<<<NGQ, 128>>>(x, w1);

    // fc2: out = spk @ w2h^T (row un-permutation in epilogue)
    hgemm_fc2<<<dim3(N2 / BN, M1 / BM), blk, SMEM_TOTAL>>>(spk, w2h, out);

    write_rate_kernel<<<1, 1>>>(out, out_size - 1);
}

// round 16
// speedup vs baseline: 1.1895x; 1.1895x over previous
#include <cuda_runtime.h>
#include <cuda_fp16.h>
#include <cstdint>
#include <cstddef>

// Problem dims (fixed)
#define M1 16384      // b*t*s = 16*4*256
#define K1 512        // d
#define N1 2048       // hidden
#define N2 512
#define HID 2048
#define N_SPIKES 33554432.0f  // 2^25

#define TAU 4e-3f
#define FCAP (1 << 22)

// ---------------------------------------------------------------------------
// Device scratch. Row order for x16 / spk is PERMUTED: row' = (b*256+s)*4 + t.
// ---------------------------------------------------------------------------
__device__ __half g_x16[(size_t)M1 * K1];     // fp16(x), (b,s,t) row order
__device__ __half g_w1h[(size_t)N1 * K1];     // fp16(w1)
__device__ __half g_spk[(size_t)M1 * HID];    // spikes (fp16), (b,s,t) rows
__device__ __half g_w2h[(size_t)N2 * HID];    // fp16(w2)
__device__ int    g_count;
__device__ int    g_nflag;
__device__ int    g_flag[FCAP];               // compact (gq*2048 + j) slots

// ---------------------------------------------------------------------------
// PTX helpers
// ---------------------------------------------------------------------------
__device__ __forceinline__ uint32_t smem_u32(const void* p) {
    uint32_t a;
    asm("{ .reg .u64 t; cvta.to.shared.u64 t, %1; cvt.u32.u64 %0, t; }" : "=r"(a) : "l"(p));
    return a;
}
__device__ __forceinline__ void cp16(uint32_t saddr, const void* g) {
    asm volatile("cp.async.cg.shared.global [%0], [%1], 16;" :: "r"(saddr), "l"(g));
}
__device__ __forceinline__ void ldm_x4(uint32_t* r, uint32_t addr) {
    asm volatile("ldmatrix.sync.aligned.m8n8.x4.shared.b16 {%0,%1,%2,%3}, [%4];"
        : "=r"(r[0]), "=r"(r[1]), "=r"(r[2]), "=r"(r[3]) : "r"(addr));
}
__device__ __forceinline__ void mma16816(float* c, const uint32_t* a, uint32_t b0, uint32_t b1) {
    asm volatile("mma.sync.aligned.m16n8k16.row.col.f32.f16.f16.f32 "
        "{%0,%1,%2,%3}, {%4,%5,%6,%7}, {%8,%9}, {%0,%1,%2,%3};"
        : "+f"(c[0]), "+f"(c[1]), "+f"(c[2]), "+f"(c[3])
        : "r"(a[0]), "r"(a[1]), "r"(a[2]), "r"(a[3]), "r"(b0), "r"(b1));
}
__device__ __forceinline__ uint32_t f2h2(float a, float b) {
    __half2 h = __floats2half2_rn(a, b);
    return *(uint32_t*)&h;
}

// ---------------------------------------------------------------------------
// GEMM config: 128x128x64 tiles, 3-stage pipeline, 8 warps (32x64 per warp)
// ---------------------------------------------------------------------------
#define BM 128
#define BN 128
#define BK 64
#define STAGES 3
#define A_STAGE_BYTES (BM * BK * 2)                 // 16384
#define STAGE_BYTES   (A_STAGE_BYTES + BN * BK * 2) // 32768
#define SMEM_TOTAL    (STAGES * STAGE_BYTES)        // 98304 (>= 128*132*4 epi)

__device__ __forceinline__ void load_stage(uint32_t s_stage, const __half* Ag,
                                           const __half* Bg, int K, int k0, int tid) {
#pragma unroll
    for (int i = 0; i < 4; i++) {
        int c = tid + i * 256;
        int row = c >> 3, kc = c & 7;
        cp16(s_stage + row * 128 + ((kc ^ (row & 7)) << 4), Ag + (long)row * K + k0 + kc * 8);
    }
#pragma unroll
    for (int i = 0; i < 4; i++) {
        int c = tid + i * 256;
        int row = c >> 3, kc = c & 7;
        cp16(s_stage + A_STAGE_BYTES + row * 128 + ((kc ^ (row & 7)) << 4),
             Bg + (long)row * K + k0 + kc * 8);
    }
}

// Fragment load for one k16 step into register buffer `buf`
#define LOAD_FRAG(buf, sa_, sb_, ks_) do {                                         \
    const int kch_ = ((ks_) << 1) + (lane >> 4);                                   \
    _Pragma("unroll")                                                              \
    for (int mt = 0; mt < 2; mt++) {                                               \
        int row = wm * 32 + mt * 16 + (lane & 15);                                 \
        ldm_x4(arf[buf][mt], (sa_) + row * 128 + ((kch_ ^ (row & 7)) << 4));       \
    }                                                                              \
    _Pragma("unroll")                                                              \
    for (int np = 0; np < 4; np++) {                                               \
        int row = wn * 64 + np * 16 + (lane & 15);                                 \
        ldm_x4(brf[buf][np], (sb_) + row * 128 + ((kch_ ^ (row & 7)) << 4));       \
    }                                                                              \
} while (0)

#define MMA_BLOCK(cur)                                                             \
    _Pragma("unroll")                                                              \
    for (int mt = 0; mt < 2; mt++)                                                 \
        _Pragma("unroll")                                                          \
        for (int nt = 0; nt < 8; nt++)                                             \
            mma16816(acc[mt][nt], arf[cur][mt], brf[cur][nt >> 1][nt & 1],         \
                     brf[cur][nt >> 1][(nt & 1) + 2]);

// ---------------------------------------------------------------------------
// fc1 + fused LIF: A rows (b,s,t)-ordered fp16; epilogue scans t in-tile,
// writes fp16 spikes, emits compact flag slots, counts unflagged spikes.
// ---------------------------------------------------------------------------
__global__ __launch_bounds__(256, 2) void hgemm_fc1_lif(const __half* __restrict__ A,
                                                        const __half* __restrict__ B) {
    extern __shared__ char sm[];
    const uint32_t s_base = smem_u32(sm);
    const int tid = threadIdx.x;
    const int wid = tid >> 5, lane = tid & 31;
    const int wm = wid & 3;
    const int wn = wid >> 2;
    const long bm = (long)blockIdx.y * BM;
    const long bn = (long)blockIdx.x * BN;

    const __half* Ag = A + bm * K1;
    const __half* Bg = B + bn * K1;

    float acc[2][8][4];
    uint32_t arf[2][2][4];
    uint32_t brf[2][4][4];
#pragma unroll
    for (int mt = 0; mt < 2; mt++)
#pragma unroll
        for (int nt = 0; nt < 8; nt++)
#pragma unroll
            for (int i = 0; i < 4; i++) acc[mt][nt][i] = 0.0f;

    const int iters = K1 / BK;
    load_stage(s_base, Ag, Bg, K1, 0, tid);
    asm volatile("cp.async.commit_group;" ::: "memory");
    load_stage(s_base + STAGE_BYTES, Ag, Bg, K1, BK, tid);
    asm volatile("cp.async.commit_group;" ::: "memory");
    for (int it = 0; it < iters; it++) {
        asm volatile("cp.async.wait_group 1;" ::: "memory");
        __syncthreads();
        const uint32_t sa = s_base + (it % STAGES) * STAGE_BYTES;
        const uint32_t sb = sa + A_STAGE_BYTES;
        LOAD_FRAG(0, sa, sb, 0);
        const int nst = it + 2;
        if (nst < iters)
            load_stage(s_base + (nst % STAGES) * STAGE_BYTES, Ag, Bg, K1, nst * BK, tid);
        asm volatile("cp.async.commit_group;" ::: "memory");
#pragma unroll
        for (int ks = 0; ks < 4; ks++) {
            const int cur = ks & 1;
            if (ks < 3) LOAD_FRAG(cur ^ 1, sa, sb, ks + 1);
            MMA_BLOCK(cur)
        }
    }

    asm volatile("cp.async.wait_group 0;" ::: "memory");
    __syncthreads();

    // spill accumulators to smem
    float* smf = (float*)sm;                 // [128][132]
#pragma unroll
    for (int mt = 0; mt < 2; mt++)
#pragma unroll
        for (int nt = 0; nt < 8; nt++) {
            int r0 = wm * 32 + mt * 16 + (lane >> 2);
            int c  = wn * 64 + nt * 8 + (lane & 3) * 2;
            smf[r0 * 132 + c]       = acc[mt][nt][0];
            smf[r0 * 132 + c + 1]   = acc[mt][nt][1];
            smf[(r0 + 8) * 132 + c]     = acc[mt][nt][2];
            smf[(r0 + 8) * 132 + c + 1] = acc[mt][nt][3];
        }
    __syncthreads();

    // LIF scan: 32 groups x 128 cols; compact slot list via warp-aggregated atomics
    const __half one  = __float2half_rn(1.0f);
    const __half zero = __float2half_rn(0.0f);
    int total = 0;
#pragma unroll
    for (int k16 = 0; k16 < 16; k16++) {
        int id = tid + k16 * 256;
        int q  = id >> 7;
        int c  = id & 127;
        long gq = blockIdx.y * 32 + q;
        long j  = bn + c;

        float v = 0.0f;
        int cnt = 0;
        bool flagged = false;
#pragma unroll
        for (int t = 0; t < 4; t++) {
            float h = smf[(4 * q + t) * 132 + c];
            v = fmaf(0.95f, v, h);
            flagged |= fabsf(v - 1.0f) < TAU;
            bool fire = (v - 1.0f) > 0.0f;
            g_spk[(gq * 4 + t) * HID + j] = fire ? one : zero;
            cnt += fire ? 1 : 0;
            v = fire ? 0.0f : v;
        }
        uint32_t fmask = __ballot_sync(0xffffffffu, flagged);
        if (fmask) {
            int leader = __ffs(fmask) - 1;
            int base = 0;
            if (lane == leader) base = atomicAdd(&g_nflag, __popc(fmask));
            base = __shfl_sync(0xffffffffu, base, leader);
            if (flagged) {
                int slot = base + __popc(fmask & ((1u << lane) - 1));
                if (slot < FCAP) g_flag[slot] = (int)(gq * 2048 + j);
            }
        }
        if (!flagged) total += cnt;          // flagged counted in fixup
    }
#pragma unroll
    for (int o = 16; o > 0; o >>= 1) total += __shfl_down_sync(0xffffffffu, total, o);
    if (lane == 0 && total) atomicAdd(&g_count, total);
}

// ---------------------------------------------------------------------------
// fc2: spikes (fp16) x w2h; epilogue un-permutes rows (b,s,t)->(b,t,s).
// Also writes the rate scalar (g_count is final: fixup precedes fc2).
// ---------------------------------------------------------------------------
__global__ __launch_bounds__(256, 2) void hgemm_fc2(const __half* __restrict__ A,
                                                    const __half* __restrict__ B,
                                                    float* __restrict__ C,
                                                    int rate_pos) {
    extern __shared__ char sm[];
    const uint32_t s_base = smem_u32(sm);
    const int tid = threadIdx.x;
    const int wid = tid >> 5, lane = tid & 31;
    const int wm = wid & 3;
    const int wn = wid >> 2;
    const long bm = (long)blockIdx.y * BM;
    const long bn = (long)blockIdx.x * BN;

    if (blockIdx.x == 0 && blockIdx.y == 0 && tid == 0)
        C[rate_pos] = (float)g_count * (1.0f / N_SPIKES);  // exact: count / 2^25

    const __half* Ag = A + bm * HID;
    const __half* Bg = B + bn * HID;

    float acc[2][8][4];
    uint32_t arf[2][2][4];
    uint32_t brf[2][4][4];
#pragma unroll
    for (int mt = 0; mt < 2; mt++)
#pragma unroll
        for (int nt = 0; nt < 8; nt++)
#pragma unroll
            for (int i = 0; i < 4; i++) acc[mt][nt][i] = 0.0f;

    const int iters = HID / BK;
    load_stage(s_base, Ag, Bg, HID, 0, tid);
    asm volatile("cp.async.commit_group;" ::: "memory");
    load_stage(s_base + STAGE_BYTES, Ag, Bg, HID, BK, tid);
    asm volatile("cp.async.commit_group;" ::: "memory");
    for (int it = 0; it < iters; it++) {
        asm volatile("cp.async.wait_group 1;" ::: "memory");
        __syncthreads();
        const uint32_t sa = s_base + (it % STAGES) * STAGE_BYTES;
        const uint32_t sb = sa + A_STAGE_BYTES;
        LOAD_FRAG(0, sa, sb, 0);
        const int nst = it + 2;
        if (nst < iters)
            load_stage(s_base + (nst % STAGES) * STAGE_BYTES, Ag, Bg, HID, nst * BK, tid);
        asm volatile("cp.async.commit_group;" ::: "memory");
#pragma unroll
        for (int ks = 0; ks < 4; ks++) {
            const int cur = ks & 1;
            if (ks < 3) LOAD_FRAG(cur ^ 1, sa, sb, ks + 1);
            MMA_BLOCK(cur)
        }
    }

    // epilogue: map row' (b,s,t) -> out row (b,t,s)
#pragma unroll
    for (int mt = 0; mt < 2; mt++)
#pragma unroll
        for (int nt = 0; nt < 8; nt++) {
            long rp0 = bm + wm * 32 + mt * 16 + (lane >> 2);
            long rp1 = rp0 + 8;
            long c = bn + wn * 64 + nt * 8 + (lane & 3) * 2;
            long b0 = rp0 >> 10, s0 = (rp0 >> 2) & 255, t0 = rp0 & 3;
            long b1 = rp1 >> 10, s1 = (rp1 >> 2) & 255, t1 = rp1 & 3;
            long r0 = b0 * 1024 + t0 * 256 + s0;
            long r1 = b1 * 1024 + t1 * 256 + s1;
            *(float2*)(C + r0 * N2 + c) = make_float2(acc[mt][nt][0], acc[mt][nt][1]);
            *(float2*)(C + r1 * N2 + c) = make_float2(acc[mt][nt][2], acc[mt][nt][3]);
        }
}

// ---------------------------------------------------------------------------
// prep: casts x (8 floats/thread, one 16B store, (b,t,s)->(b,s,t) rows), w1, w2
// ---------------------------------------------------------------------------
#define X8   (M1 * K1 / 8)      // 1048576
#define W14  (N1 * K1 / 4)      // 262144
#define W24  (N2 * HID / 4)     // 262144

__global__ __launch_bounds__(256) void prep_kernel(const float* __restrict__ x,
                                                   const float* __restrict__ w1,
                                                   const float* __restrict__ w2) {
    int i = blockIdx.x * blockDim.x + threadIdx.x;
    if (i == 0) { g_count = 0; g_nflag = 0; }
    if (i < X8) {
        int row = i >> 6, wi = i & 63;       // 64 chunks of 8 floats per row
        int b = row >> 10, t = (row >> 8) & 3, s = row & 255;
        long newrow = (((long)b * 256 + s) * 4 + t);
        const float4* src = (const float4*)x + (size_t)row * 128 + wi * 2;
        float4 v0 = __ldg(src);
        float4 v1 = __ldg(src + 1);
        uint4 u;
        u.x = f2h2(v0.x, v0.y);
        u.y = f2h2(v0.z, v0.w);
        u.z = f2h2(v1.x, v1.y);
        u.w = f2h2(v1.z, v1.w);
        *(uint4*)(g_x16 + newrow * K1 + wi * 8) = u;
    } else if (i < X8 + W14) {
        int k = i - X8;
        float4 v = __ldg((const float4*)w1 + k);
        ((__half2*)g_w1h)[2 * k]     = __floats2half2_rn(v.x, v.y);
        ((__half2*)g_w1h)[2 * k + 1] = __floats2half2_rn(v.z, v.w);
    } else if (i < X8 + W14 + W24) {
        int k = i - X8 - W14;
        float4 v = __ldg((const float4*)w2 + k);
        ((__half2*)g_w2h)[2 * k]     = __floats2half2_rn(v.x, v.y);
        ((__half2*)g_w2h)[2 * k + 1] = __floats2half2_rn(v.z, v.w);
    }
}

// ---------------------------------------------------------------------------
// Fixup v5 (dense): grid-stride, thread = (flagged-neuron, timestep).
// Every chain is the PROVEN serial ascending-k fp32 fmaf order (0 flips).
// Quad shfl gathers the 4 h's; lane tt=0 scans, writes spikes, counts.
// ---------------------------------------------------------------------------
__global__ __launch_bounds__(256) void fixup_kernel(const float* __restrict__ x,
                                                    const float* __restrict__ w1) {
    int n = g_nflag;
    if (n > FCAP) n = FCAP;
    const int nwork = 4 * n;
    const int stride = gridDim.x * blockDim.x;
    const int lane = threadIdx.x & 31;
    const __half one  = __float2half_rn(1.0f);
    const __half zero = __float2half_rn(0.0f);

    for (int base0 = blockIdx.x * blockDim.x; base0 < nwork; base0 += stride) {
        int gid = base0 + threadIdx.x;
        bool active = gid < nwork;
        int li = active ? (gid >> 2) : 0;
        int tt = gid & 3;
        int idx = active ? g_flag[li] : 0;
        int j  = idx & (HID - 1);
        int gq = idx >> 11;
        int b  = gq >> 8, s = gq & 255;
        const float4* wrow = (const float4*)(w1 + (size_t)j * K1);
        const float4* xrow = (const float4*)(x + (((size_t)b * 4 + tt) * 256 + s) * K1);

        float h = 0.0f;
#pragma unroll 8
        for (int k4 = 0; k4 < 128; k4++) {
            float4 wv = __ldg(wrow + k4);
            float4 xv = __ldg(xrow + k4);
            h = fmaf(xv.x, wv.x, h);
            h = fmaf(xv.y, wv.y, h);
            h = fmaf(xv.z, wv.z, h);
            h = fmaf(xv.w, wv.w, h);
        }
        float hs[4];
#pragma unroll
        for (int k = 0; k < 4; k++)
            hs[k] = __shfl_sync(0xffffffffu, h, (lane & ~3) | k);

        int c = 0;
        if (active && tt == 0) {
            float v = 0.0f;
#pragma unroll
            for (int t2 = 0; t2 < 4; t2++) {
                v = fmaf(0.95f, v, hs[t2]);
                bool fire = (v - 1.0f) > 0.0f;
                g_spk[((size_t)gq * 4 + t2) * HID + j] = fire ? one : zero;
                c += fire ? 1 : 0;
                v = fire ? 0.0f : v;
            }
        }
#pragma unroll
        for (int o = 16; o > 0; o >>= 1) c += __shfl_down_sync(0xffffffffu, c, o);
        if (lane == 0 && c) atomicAdd(&g_count, c);
    }
}

// ---------------------------------------------------------------------------
extern "C" void kernel_launch(void* const* d_in, const int* in_sizes, int n_in,
                              void* d_out, int out_size) {
    const float* x  = (const float*)d_in[0];  // (16,4,256,512)
    const float* w1 = (const float*)d_in[1];  // (2048,512)
    const float* w2 = (const float*)d_in[2];  // (512,2048)
    float* out = (float*)d_out;

    __half *x16, *w1h, *spk, *w2h;
    cudaGetSymbolAddress((void**)&x16, g_x16);
    cudaGetSymbolAddress((void**)&w1h, g_w1h);
    cudaGetSymbolAddress((void**)&spk, g_spk);
    cudaGetSymbolAddress((void**)&w2h, g_w2h);

    cudaFuncSetAttribute(hgemm_fc1_lif, cudaFuncAttributeMaxDynamicSharedMemorySize, SMEM_TOTAL);
    cudaFuncSetAttribute(hgemm_fc2, cudaFuncAttributeMaxDynamicSharedMemorySize, SMEM_TOTAL);

    dim3 blk(256);

    // casts + counter zeroing
    prep_kernel<<<(X8 + W14 + W24 + 255) / 256, blk>>>(x, w1, w2);

    // fc1 + fused LIF scan (fp16 spikes + compact flag list; counts unflagged)
    hgemm_fc1_lif<<<dim3(N1 / BN, M1 / BM), blk, SMEM_TOTAL>>>(x16, w1h);

    // dense exact fixup: thread = (flagged neuron, timestep)
    fixup_kernel<<<1024, blk>>>(x, w1);

    // fc2: out = spk @ w2h^T (un-permute in epilogue) + rate scalar write
    hgemm_fc2<<<dim3(N2 / BN, M1 / BM), blk, SMEM_TOTAL>>>(spk, w2h, out, out_size - 1);
}